// round 7
// baseline (speedup 1.0000x reference)
#include <cuda_runtime.h>
#include <cstdint>

// Problem constants (fixed shapes from reference)
#define BB 2
#define TT 2048
#define DD 512
#define HH 8
#define DH 64
#define SCALE 0.125f   // 64^-0.5

// Scratch: Qp[b,q,h,d] (conv folded into query, scale folded), bias dot per (b,q,h)
__device__ float g_Qp[BB * TT * DD];   // 8.4 MB
__device__ float g_bq[BB * TT * HH];

typedef unsigned long long u64;

__device__ __forceinline__ u64 ffma2(u64 a, u64 b, u64 c) {
    u64 d;
    asm("fma.rn.f32x2 %0, %1, %2, %3;" : "=l"(d) : "l"(a), "l"(b), "l"(c));
    return d;
}
__device__ __forceinline__ float2 unpk(u64 a) {
    float2 r;
    asm("mov.b64 {%0,%1}, %2;" : "=f"(r.x), "=f"(r.y) : "l"(a));
    return r;
}
__device__ __forceinline__ u64 pk2(float x) {
    u64 r;
    asm("mov.b64 %0, {%1,%1};" : "=l"(r) : "f"(x));
    return r;
}
__device__ __forceinline__ uint32_t smem_u32(const void* p) {
    uint32_t a;
    asm("{ .reg .u64 t; cvta.to.shared.u64 t, %1; cvt.u32.u64 %0, t; }"
        : "=r"(a) : "l"(p));
    return a;
}
__device__ __forceinline__ void cp16(uint32_t dst, const void* src) {
    asm volatile("cp.async.cg.shared.global [%0], [%1], 16;" :: "r"(dst), "l"(src));
}
#define CP_COMMIT()  asm volatile("cp.async.commit_group;")
#define CP_WAIT(N)   asm volatile("cp.async.wait_group %0;" :: "n"(N))

// ---------------------------------------------------------------------------
// Kernel 1: Qp[row, h*64+d] = SCALE * sum_j query[row, h*64+j] * conv_w[h*64+j, d]
//           bq[row, h]      = SCALE * sum_j query[row, h*64+j] * conv_b[h*64+j]
// ---------------------------------------------------------------------------
#define TQ1 16
__global__ __launch_bounds__(256) void prep_kernel(
    const float* __restrict__ query,
    const float* __restrict__ conv_w,
    const float* __restrict__ conv_b)
{
    __shared__ __align__(16) float q_sh[TQ1][DD];   // 32 KB
    const int q0 = blockIdx.x * TQ1;                // row base in [0, B*T)
    const int t  = threadIdx.x;

    const float4* qg = (const float4*)(query + (size_t)q0 * DD);
    float4* qs = (float4*)&q_sh[0][0];
    #pragma unroll
    for (int i = 0; i < TQ1 * DD / 4 / 256; ++i)    // 8
        qs[t + i * 256] = qg[t + i * 256];
    __syncthreads();

    // bias dot terms (conv_b is zero in this dataset, but keep it general)
    if (t < TQ1 * HH) {                             // 128 threads
        int q = t >> 3, h = t & 7;
        float acc = 0.f;
        #pragma unroll
        for (int j = 0; j < DH; ++j)
            acc += q_sh[q][h * DH + j] * __ldg(conv_b + h * DH + j);
        g_bq[(q0 + q) * HH + h] = SCALE * acc;
    }

    #pragma unroll 1
    for (int cc = 0; cc < 2; ++cc) {
        int c = t + cc * 256;                       // output column 0..511
        int h = c >> 6;
        float W[DH];
        #pragma unroll
        for (int j = 0; j < DH; ++j)
            W[j] = __ldg(conv_w + (h * DH + j) * DH + (c & 63));
        #pragma unroll 1
        for (int q = 0; q < TQ1; ++q) {
            const float4* qr = (const float4*)&q_sh[q][h * DH];
            float acc = 0.f;
            #pragma unroll
            for (int i = 0; i < 16; ++i) {
                float4 v = qr[i];
                acc += W[4*i+0] * v.x + W[4*i+1] * v.y
                     + W[4*i+2] * v.z + W[4*i+3] * v.w;
            }
            g_Qp[(size_t)(q0 + q) * DD + c] = SCALE * acc;
        }
    }
}

// ---------------------------------------------------------------------------
// Kernel 2: fused scores + head-softmax + context.
// Block = 256 threads = 8 q-rows x 8 heads x 4 d-quarters (one q-row / warp).
// Lane layout: h = bits[2:0] (softmax group), e = bits[4:3] (d-quarter).
// Thread (q,h,e) holds 16 floats of Qp and 16 of ctx -> ~72 regs total,
// 3 blocks/SM (24 warps) for latency coverage.
// Score fold: shfl_xor 8,16 over d-quarters; softmax: shfl_xor 1,2,4 over h.
// Two-phase per 4-key chunk (batched softmax = 4 parallel latency chains).
// V tiles (64 keys x 64 d) double-buffered in SMEM via cp.async.
// ---------------------------------------------------------------------------
#define TQ 8
#define KT 64
#define KJ 4
#define NTILES (TT / KT)
__global__ __launch_bounds__(256, 3) void attn_kernel(
    const float* __restrict__ value,
    float* __restrict__ out)
{
    __shared__ __align__(16) float v_sh[2][KT * DH];   // 2 x 16 KB
    const int b  = blockIdx.y;
    const int q0 = blockIdx.x * TQ;
    const int t  = threadIdx.x;
    const int h  = t & 7;           // softmax group (8 heads)
    const int e  = (t >> 3) & 3;    // d-quarter
    const int ql = t >> 5;          // 0..7 (warp id)
    const int row = b * TT + q0 + ql;

    // This thread's quarter of Qp[row, h, :]: 16 floats = 8 packed f32x2
    u64 qp2[8];
    {
        const longlong2* qpg =
            (const longlong2*)(g_Qp + (size_t)row * DD + h * DH + e * 16);
        #pragma unroll
        for (int i = 0; i < 4; ++i) {
            longlong2 v = qpg[i];
            qp2[2*i]     = (u64)v.x;
            qp2[2*i + 1] = (u64)v.y;
        }
    }
    const float ebq = __expf(g_bq[row * HH + h]);   // bias folded into exp

    u64 ctx2[8];
    #pragma unroll
    for (int i = 0; i < 8; ++i) ctx2[i] = 0ULL;

    const char* vbase = (const char*)(value + (size_t)b * TT * DH);
    const uint32_t sb[2] = { smem_u32(&v_sh[0][0]), smem_u32(&v_sh[1][0]) };

    // Prologue: stage tile 0 (16 KB: 4 x 16B per thread)
    {
        const char* src = vbase + t * 16;
        #pragma unroll
        for (int i = 0; i < 4; ++i)
            cp16(sb[0] + t * 16 + i * 4096, src + i * 4096);
        CP_COMMIT();
    }

    #pragma unroll 1
    for (int tile = 0; tile < NTILES; ++tile) {
        // Prefetch next tile into the other buffer
        if (tile + 1 < NTILES) {
            const char* src = vbase + (size_t)(tile + 1) * (KT * DH * 4) + t * 16;
            uint32_t dbuf = sb[(tile + 1) & 1];
            #pragma unroll
            for (int i = 0; i < 4; ++i)
                cp16(dbuf + t * 16 + i * 4096, src + i * 4096);
            CP_COMMIT();
            CP_WAIT(1);     // current tile's group done
        } else {
            CP_WAIT(0);
        }
        __syncthreads();

        const longlong2* Vs = (const longlong2*)&v_sh[tile & 1][0];

        #pragma unroll 1
        for (int tt0 = 0; tt0 < KT; tt0 += KJ) {
            // ---- Phase A: scores for KJ keys (quarter-dot + xor folds) ----
            float s[KJ];
            #pragma unroll
            for (int j = 0; j < KJ; ++j) {
                const longlong2* vr = Vs + (tt0 + j) * 16 + e * 4;
                u64 a0 = 0ULL, a1 = 0ULL;
                #pragma unroll
                for (int i = 0; i < 4; ++i) {
                    longlong2 vq = vr[i];          // 4-address LDS.128
                    a0 = ffma2(qp2[2*i],     (u64)vq.x, a0);
                    a1 = ffma2(qp2[2*i + 1], (u64)vq.y, a1);
                }
                float2 p0 = unpk(a0), p1 = unpk(a1);
                float p = (p0.x + p0.y) + (p1.x + p1.y);
                p += __shfl_xor_sync(0xffffffffu, p, 8);    // fold d-quarters
                p += __shfl_xor_sync(0xffffffffu, p, 16);
                s[j] = p;
            }

            // ---- Softmax over 8 heads (|s| small: no max-subtract) ----
            float w[KJ];
            #pragma unroll
            for (int j = 0; j < KJ; ++j) {
                float ex = __expf(s[j]) * ebq;
                float sm = ex;
                sm += __shfl_xor_sync(0xffffffffu, sm, 1);
                sm += __shfl_xor_sync(0xffffffffu, sm, 2);
                sm += __shfl_xor_sync(0xffffffffu, sm, 4);
                w[j] = __fdividef(ex, sm);
            }

            // ---- Phase B: rank-KJ context update on this d-quarter ----
            #pragma unroll
            for (int j = 0; j < KJ; ++j) {
                u64 w2 = pk2(w[j]);
                const longlong2* vr = Vs + (tt0 + j) * 16 + e * 4;
                #pragma unroll
                for (int i = 0; i < 4; ++i) {
                    longlong2 vq = vr[i];
                    ctx2[2*i]     = ffma2(w2, (u64)vq.x, ctx2[2*i]);
                    ctx2[2*i + 1] = ffma2(w2, (u64)vq.y, ctx2[2*i + 1]);
                }
            }
        }
        __syncthreads();   // protect buffer before next prefetch overwrites it
    }

    // out[b, q, h*64 + e*16 + d]
    float* op = out + (size_t)row * DD + h * DH + e * 16;
    #pragma unroll
    for (int i = 0; i < 4; ++i) {
        longlong2 vv;
        vv.x = (long long)ctx2[2*i];
        vv.y = (long long)ctx2[2*i + 1];
        ((longlong2*)op)[i] = vv;
    }
}

extern "C" void kernel_launch(void* const* d_in, const int* in_sizes, int n_in,
                              void* d_out, int out_size) {
    const float* query  = (const float*)d_in[0];   // [2,2048,512]
    const float* value  = (const float*)d_in[1];   // [2,2048,64]
    const float* conv_w = (const float*)d_in[2];   // [512,64,1]
    const float* conv_b = (const float*)d_in[3];   // [512]
    float* out = (float*)d_out;                    // [2,2048,512]

    prep_kernel<<<BB * TT / TQ1, 256>>>(query, conv_w, conv_b);
    dim3 grid(TT / TQ, BB);
    attn_kernel<<<grid, 256>>>(value, out);
}

// round 8
// speedup vs baseline: 1.0242x; 1.0242x over previous
#include <cuda_runtime.h>
#include <cstdint>

// Problem constants (fixed shapes from reference)
#define BB 2
#define TT 2048
#define DD 512
#define HH 8
#define DH 64
#define SCALE 0.125f   // 64^-0.5

// Scratch: Qp[b,q,h,d] (conv folded into query, scale folded), bias dot per (b,q,h)
__device__ float g_Qp[BB * TT * DD];   // 8.4 MB
__device__ float g_bq[BB * TT * HH];

typedef unsigned long long u64;

__device__ __forceinline__ u64 ffma2(u64 a, u64 b, u64 c) {
    u64 d;
    asm("fma.rn.f32x2 %0, %1, %2, %3;" : "=l"(d) : "l"(a), "l"(b), "l"(c));
    return d;
}
__device__ __forceinline__ float2 unpk(u64 a) {
    float2 r;
    asm("mov.b64 {%0,%1}, %2;" : "=f"(r.x), "=f"(r.y) : "l"(a));
    return r;
}
__device__ __forceinline__ u64 pk2(float x) {
    u64 r;
    asm("mov.b64 %0, {%1,%1};" : "=l"(r) : "f"(x));
    return r;
}
__device__ __forceinline__ uint32_t smem_u32(const void* p) {
    uint32_t a;
    asm("{ .reg .u64 t; cvta.to.shared.u64 t, %1; cvt.u32.u64 %0, t; }"
        : "=r"(a) : "l"(p));
    return a;
}
__device__ __forceinline__ void cp16(uint32_t dst, const void* src) {
    asm volatile("cp.async.cg.shared.global [%0], [%1], 16;" :: "r"(dst), "l"(src));
}
#define CP_COMMIT()  asm volatile("cp.async.commit_group;")
#define CP_WAIT(N)   asm volatile("cp.async.wait_group %0;" :: "n"(N))

// ---------------------------------------------------------------------------
// Kernel 1: Qp[row, h*64+d] = SCALE * sum_j query[row, h*64+j] * conv_w[h*64+j, d]
//           bq[row, h]      = SCALE * sum_j query[row, h*64+j] * conv_b[h*64+j]
// ---------------------------------------------------------------------------
#define TQ1 16
__global__ __launch_bounds__(256) void prep_kernel(
    const float* __restrict__ query,
    const float* __restrict__ conv_w,
    const float* __restrict__ conv_b)
{
    __shared__ __align__(16) float q_sh[TQ1][DD];   // 32 KB
    const int q0 = blockIdx.x * TQ1;                // row base in [0, B*T)
    const int t  = threadIdx.x;

    const float4* qg = (const float4*)(query + (size_t)q0 * DD);
    float4* qs = (float4*)&q_sh[0][0];
    #pragma unroll
    for (int i = 0; i < TQ1 * DD / 4 / 256; ++i)    // 8
        qs[t + i * 256] = qg[t + i * 256];
    __syncthreads();

    // bias dot terms (conv_b is zero in this dataset, but keep it general)
    if (t < TQ1 * HH) {                             // 128 threads
        int q = t >> 3, h = t & 7;
        float acc = 0.f;
        #pragma unroll
        for (int j = 0; j < DH; ++j)
            acc += q_sh[q][h * DH + j] * __ldg(conv_b + h * DH + j);
        g_bq[(q0 + q) * HH + h] = SCALE * acc;
    }

    #pragma unroll 1
    for (int cc = 0; cc < 2; ++cc) {
        int c = t + cc * 256;                       // output column 0..511
        int h = c >> 6;
        float W[DH];
        #pragma unroll
        for (int j = 0; j < DH; ++j)
            W[j] = __ldg(conv_w + (h * DH + j) * DH + (c & 63));
        #pragma unroll 1
        for (int q = 0; q < TQ1; ++q) {
            const float4* qr = (const float4*)&q_sh[q][h * DH];
            float acc = 0.f;
            #pragma unroll
            for (int i = 0; i < 16; ++i) {
                float4 v = qr[i];
                acc += W[4*i+0] * v.x + W[4*i+1] * v.y
                     + W[4*i+2] * v.z + W[4*i+3] * v.w;
            }
            g_Qp[(size_t)(q0 + q) * DD + c] = SCALE * acc;
        }
    }
}

// ---------------------------------------------------------------------------
// Kernel 2: fused scores + head-softmax + context.
// Block = 256 threads = 8 q-rows x 8 heads x 4 d-quarters (one q-row / warp).
// Lane layout: h = bits[2:0] (softmax group), e = bits[4:3] (d-quarter).
// Lane e owns the 16B d-chunks c == e (mod 4) of each 64-float V row, so the
// 4 lane addresses per LDS.128 are 64B contiguous -> conflict-free.
// Per 4-key chunk: partial dots, 4x4 e<->key register transpose (4 shfl),
// ONE exp + 3-shfl h-softmax + ONE div per lane, 3-shfl weight allgather,
// rank-4 context update. 10 shfl + 2 MUFU per chunk (was 20 + 8).
// __launch_bounds__(256,4): <=64 regs -> 4 blocks/SM -> grid 512 in ONE wave.
// V tiles (64 keys x 64 d) double-buffered in SMEM via cp.async.
// ---------------------------------------------------------------------------
#define TQ 8
#define KT 64
#define NTILES (TT / KT)
__global__ __launch_bounds__(256, 4) void attn_kernel(
    const float* __restrict__ value,
    float* __restrict__ out)
{
    __shared__ __align__(16) float v_sh[2][KT * DH];   // 2 x 16 KB
    const int b  = blockIdx.y;
    const int q0 = blockIdx.x * TQ;
    const int t  = threadIdx.x;
    const int h  = t & 7;           // softmax group (8 heads)
    const int e  = (t >> 3) & 3;    // d-quarter / key-slot id
    const int ql = t >> 5;          // 0..7 (warp id)
    const int row = b * TT + q0 + ql;
    const bool elo1 = (e & 1) == 0;
    const bool elo2 = (e & 2) == 0;

    // This thread's d-chunks of Qp[row, h, :]: chunks c = 4i+e (16B each)
    u64 qp2[8];
    {
        const longlong2* qpg = (const longlong2*)(g_Qp + (size_t)row * DD + h * DH);
        #pragma unroll
        for (int i = 0; i < 4; ++i) {
            longlong2 v = qpg[i * 4 + e];
            qp2[2*i]     = (u64)v.x;
            qp2[2*i + 1] = (u64)v.y;
        }
    }
    const float ebq = __expf(g_bq[row * HH + h]);   // bias folded into exp

    u64 ctx2[8];
    #pragma unroll
    for (int i = 0; i < 8; ++i) ctx2[i] = 0ULL;

    const char* vbase = (const char*)(value + (size_t)b * TT * DH);
    const uint32_t sb[2] = { smem_u32(&v_sh[0][0]), smem_u32(&v_sh[1][0]) };

    // Prologue: stage tile 0 (16 KB: 4 x 16B per thread)
    {
        const char* src = vbase + t * 16;
        #pragma unroll
        for (int i = 0; i < 4; ++i)
            cp16(sb[0] + t * 16 + i * 4096, src + i * 4096);
        CP_COMMIT();
    }

    #pragma unroll 1
    for (int tile = 0; tile < NTILES; ++tile) {
        // Prefetch next tile into the other buffer
        if (tile + 1 < NTILES) {
            const char* src = vbase + (size_t)(tile + 1) * (KT * DH * 4) + t * 16;
            uint32_t dbuf = sb[(tile + 1) & 1];
            #pragma unroll
            for (int i = 0; i < 4; ++i)
                cp16(dbuf + t * 16 + i * 4096, src + i * 4096);
            CP_COMMIT();
            CP_WAIT(1);     // current tile's group done
        } else {
            CP_WAIT(0);
        }
        __syncthreads();

        const longlong2* Vs = (const longlong2*)&v_sh[tile & 1][0];

        #pragma unroll 1
        for (int tt0 = 0; tt0 < KT; tt0 += 4) {
            // ---- Partial dots: key tt0+j over my d-chunks (4i+e) ----
            float p[4];
            #pragma unroll
            for (int j = 0; j < 4; ++j) {
                const longlong2* vr = Vs + (tt0 + j) * 16;
                u64 a0 = 0ULL, a1 = 0ULL;
                #pragma unroll
                for (int i = 0; i < 4; ++i) {
                    longlong2 vq = vr[i * 4 + e];   // 64B-contiguous across e
                    a0 = ffma2(qp2[2*i],     (u64)vq.x, a0);
                    a1 = ffma2(qp2[2*i + 1], (u64)vq.y, a1);
                }
                float2 p0 = unpk(a0), p1 = unpk(a1);
                p[j] = (p0.x + p0.y) + (p1.x + p1.y);
            }

            // ---- 4x4 transpose across e: lane ends with all partials of key e
            {   // stage 1: partner e^1 (lane xor 8)
                float a = elo1 ? p[1] : p[0];
                float c = elo1 ? p[3] : p[2];
                a = __shfl_xor_sync(0xffffffffu, a, 8);
                c = __shfl_xor_sync(0xffffffffu, c, 8);
                if (elo1) { p[1] = a; p[3] = c; } else { p[0] = a; p[2] = c; }
            }
            {   // stage 2: partner e^2 (lane xor 16)
                float a = elo2 ? p[2] : p[0];
                float c = elo2 ? p[3] : p[1];
                a = __shfl_xor_sync(0xffffffffu, a, 16);
                c = __shfl_xor_sync(0xffffffffu, c, 16);
                if (elo2) { p[2] = a; p[3] = c; } else { p[0] = a; p[1] = c; }
            }
            float s = (p[0] + p[1]) + (p[2] + p[3]);   // full dot, key tt0+e

            // ---- Softmax over 8 heads for my key (|s| small: no max-sub) ----
            float ex = __expf(s) * ebq;
            float sm = ex;
            sm += __shfl_xor_sync(0xffffffffu, sm, 1);
            sm += __shfl_xor_sync(0xffffffffu, sm, 2);
            sm += __shfl_xor_sync(0xffffffffu, sm, 4);
            float w0 = __fdividef(ex, sm);             // weight of key tt0+e

            // ---- Allgather weights across e: wk = weight of key tt0+(e^k)
            float w1 = __shfl_xor_sync(0xffffffffu, w0, 8);
            float w2 = __shfl_xor_sync(0xffffffffu, w0, 16);
            float w3 = __shfl_xor_sync(0xffffffffu, w1, 16);

            // ---- Rank-4 context update on my d-chunks ----
            u64 wp[4] = { pk2(w0), pk2(w1), pk2(w2), pk2(w3) };
            #pragma unroll
            for (int k = 0; k < 4; ++k) {
                const longlong2* vr = Vs + (tt0 + (e ^ k)) * 16;
                #pragma unroll
                for (int i = 0; i < 4; ++i) {
                    longlong2 vq = vr[i * 4 + e];
                    ctx2[2*i]     = ffma2(wp[k], (u64)vq.x, ctx2[2*i]);
                    ctx2[2*i + 1] = ffma2(wp[k], (u64)vq.y, ctx2[2*i + 1]);
                }
            }
        }
        __syncthreads();   // protect buffer before next prefetch overwrites it
    }

    // out[b, q, h*64 + chunk(4i+e)]
    longlong2* op = (longlong2*)(out + (size_t)row * DD + h * DH);
    #pragma unroll
    for (int i = 0; i < 4; ++i) {
        longlong2 vv;
        vv.x = (long long)ctx2[2*i];
        vv.y = (long long)ctx2[2*i + 1];
        op[i * 4 + e] = vv;
    }
}

extern "C" void kernel_launch(void* const* d_in, const int* in_sizes, int n_in,
                              void* d_out, int out_size) {
    const float* query  = (const float*)d_in[0];   // [2,2048,512]
    const float* value  = (const float*)d_in[1];   // [2,2048,64]
    const float* conv_w = (const float*)d_in[2];   // [512,64,1]
    const float* conv_b = (const float*)d_in[3];   // [512]
    float* out = (float*)d_out;                    // [2,2048,512]

    prep_kernel<<<BB * TT / TQ1, 256>>>(query, conv_w, conv_b);
    dim3 grid(TT / TQ, BB);
    attn_kernel<<<grid, 256>>>(value, out);
}

// round 9
// speedup vs baseline: 1.2822x; 1.2519x over previous
#include <cuda_runtime.h>
#include <cstdint>

// Problem constants (fixed shapes from reference)
#define BB 2
#define TT 2048
#define DD 512
#define HH 8
#define DH 64
#define SCALE 0.125f   // 64^-0.5

// Scratch: Qp[b,q,h,d] (conv folded into query, scale folded), bias dot per (b,q,h)
__device__ float g_Qp[BB * TT * DD];   // 8.4 MB
__device__ float g_bq[BB * TT * HH];

typedef unsigned long long u64;

__device__ __forceinline__ u64 ffma2(u64 a, u64 b, u64 c) {
    u64 d;
    asm("fma.rn.f32x2 %0, %1, %2, %3;" : "=l"(d) : "l"(a), "l"(b), "l"(c));
    return d;
}
__device__ __forceinline__ float2 unpk(u64 a) {
    float2 r;
    asm("mov.b64 {%0,%1}, %2;" : "=f"(r.x), "=f"(r.y) : "l"(a));
    return r;
}
__device__ __forceinline__ u64 pk2(float x) {
    u64 r;
    asm("mov.b64 %0, {%1,%1};" : "=l"(r) : "f"(x));
    return r;
}
__device__ __forceinline__ uint32_t smem_u32(const void* p) {
    uint32_t a;
    asm("{ .reg .u64 t; cvta.to.shared.u64 t, %1; cvt.u32.u64 %0, t; }"
        : "=r"(a) : "l"(p));
    return a;
}
__device__ __forceinline__ void cp16(uint32_t dst, const void* src) {
    asm volatile("cp.async.cg.shared.global [%0], [%1], 16;" :: "r"(dst), "l"(src));
}
#define CP_COMMIT()  asm volatile("cp.async.commit_group;")
#define CP_WAIT(N)   asm volatile("cp.async.wait_group %0;" :: "n"(N))

// ---------------------------------------------------------------------------
// Kernel 1: Qp[row, h*64+d] = SCALE * sum_j query[row, h*64+j] * conv_w[h*64+j, d]
//           bq[row, h]      = SCALE * sum_j query[row, h*64+j] * conv_b[h*64+j]
// ---------------------------------------------------------------------------
#define TQ1 16
__global__ __launch_bounds__(256) void prep_kernel(
    const float* __restrict__ query,
    const float* __restrict__ conv_w,
    const float* __restrict__ conv_b)
{
    __shared__ __align__(16) float q_sh[TQ1][DD];   // 32 KB
    const int q0 = blockIdx.x * TQ1;                // row base in [0, B*T)
    const int t  = threadIdx.x;

    const float4* qg = (const float4*)(query + (size_t)q0 * DD);
    float4* qs = (float4*)&q_sh[0][0];
    #pragma unroll
    for (int i = 0; i < TQ1 * DD / 4 / 256; ++i)    // 8
        qs[t + i * 256] = qg[t + i * 256];
    __syncthreads();

    // bias dot terms (conv_b is zero in this dataset, but keep it general)
    if (t < TQ1 * HH) {                             // 128 threads
        int q = t >> 3, h = t & 7;
        float acc = 0.f;
        #pragma unroll
        for (int j = 0; j < DH; ++j)
            acc += q_sh[q][h * DH + j] * __ldg(conv_b + h * DH + j);
        g_bq[(q0 + q) * HH + h] = SCALE * acc;
    }

    #pragma unroll 1
    for (int cc = 0; cc < 2; ++cc) {
        int c = t + cc * 256;                       // output column 0..511
        int h = c >> 6;
        float W[DH];
        #pragma unroll
        for (int j = 0; j < DH; ++j)
            W[j] = __ldg(conv_w + (h * DH + j) * DH + (c & 63));
        #pragma unroll 1
        for (int q = 0; q < TQ1; ++q) {
            const float4* qr = (const float4*)&q_sh[q][h * DH];
            float acc = 0.f;
            #pragma unroll
            for (int i = 0; i < 16; ++i) {
                float4 v = qr[i];
                acc += W[4*i+0] * v.x + W[4*i+1] * v.y
                     + W[4*i+2] * v.z + W[4*i+3] * v.w;
            }
            g_Qp[(size_t)(q0 + q) * DD + c] = SCALE * acc;
        }
    }
}

// ---------------------------------------------------------------------------
// Kernel 2: fused scores + head-softmax + context, 2 q-rows per warp.
// Block = 256 threads = 8 warps; warp ql handles q-rows (ql) and (ql+8) of a
// 16-row block. Lane layout: h = bits[2:0] (softmax group), e = bits[4:3]
// (d-quarter / key-slot). Lane e owns 16B d-chunks c == e (mod 4) of each
// 64-float V row (4 lane addresses 64B-contiguous -> conflict-free).
// KEY POINT (from R8 ncu): kernel is LSU-bound. Each V chunk loaded from SMEM
// now feeds FOUR ffma2 (2 fp32x2 chains x 2 q-rows): ffma2:LDS = 4 (was 2).
// Per 4-key chunk: partial dots for both rows, 4x4 e<->key register transpose
// per row, ONE exp + 3-shfl h-softmax + ONE div per lane per row, 3-shfl
// weight allgather per row, rank-4 context update for both rows.
// V tiles (64 keys x 64 d) double-buffered in SMEM via cp.async.
// ---------------------------------------------------------------------------
#define TQ 16
#define KT 64
#define NTILES (TT / KT)
__global__ __launch_bounds__(256, 2) void attn_kernel(
    const float* __restrict__ value,
    float* __restrict__ out)
{
    __shared__ __align__(16) float v_sh[2][KT * DH];   // 2 x 16 KB
    const int b  = blockIdx.y;
    const int q0 = blockIdx.x * TQ;
    const int t  = threadIdx.x;
    const int h  = t & 7;           // softmax group (8 heads)
    const int e  = (t >> 3) & 3;    // d-quarter / key-slot id
    const int ql = t >> 5;          // warp id 0..7
    const int rowA = b * TT + q0 + ql;
    const int rowB = rowA + 8;
    const bool elo1 = (e & 1) == 0;
    const bool elo2 = (e & 2) == 0;

    // Qp d-chunks (c = 4i+e) for both rows: 8 u64 each
    u64 qpa[8], qpb[8];
    {
        const longlong2* pa = (const longlong2*)(g_Qp + (size_t)rowA * DD + h * DH);
        const longlong2* pb = (const longlong2*)(g_Qp + (size_t)rowB * DD + h * DH);
        #pragma unroll
        for (int i = 0; i < 4; ++i) {
            longlong2 va = pa[i * 4 + e];
            longlong2 vb = pb[i * 4 + e];
            qpa[2*i] = (u64)va.x;  qpa[2*i+1] = (u64)va.y;
            qpb[2*i] = (u64)vb.x;  qpb[2*i+1] = (u64)vb.y;
        }
    }
    const float ebqA = __expf(g_bq[rowA * HH + h]);
    const float ebqB = __expf(g_bq[rowB * HH + h]);

    u64 cta[8], ctb[8];
    #pragma unroll
    for (int i = 0; i < 8; ++i) { cta[i] = 0ULL; ctb[i] = 0ULL; }

    const char* vbase = (const char*)(value + (size_t)b * TT * DH);
    const uint32_t sb[2] = { smem_u32(&v_sh[0][0]), smem_u32(&v_sh[1][0]) };

    // Prologue: stage tile 0 (16 KB: 4 x 16B per thread)
    {
        const char* src = vbase + t * 16;
        #pragma unroll
        for (int i = 0; i < 4; ++i)
            cp16(sb[0] + t * 16 + i * 4096, src + i * 4096);
        CP_COMMIT();
    }

    #pragma unroll 1
    for (int tile = 0; tile < NTILES; ++tile) {
        if (tile + 1 < NTILES) {
            const char* src = vbase + (size_t)(tile + 1) * (KT * DH * 4) + t * 16;
            uint32_t dbuf = sb[(tile + 1) & 1];
            #pragma unroll
            for (int i = 0; i < 4; ++i)
                cp16(dbuf + t * 16 + i * 4096, src + i * 4096);
            CP_COMMIT();
            CP_WAIT(1);
        } else {
            CP_WAIT(0);
        }
        __syncthreads();

        const longlong2* Vs = (const longlong2*)&v_sh[tile & 1][0];

        #pragma unroll 1
        for (int tt0 = 0; tt0 < KT; tt0 += 4) {
            // ---- Phase A: partial dots for both rows (V loaded once) ----
            float pa[4], pb[4];
            #pragma unroll
            for (int j = 0; j < 4; ++j) {
                const longlong2* vr = Vs + (tt0 + j) * 16;
                u64 a0 = 0ULL, a1 = 0ULL, b0 = 0ULL, b1 = 0ULL;
                #pragma unroll
                for (int i = 0; i < 4; ++i) {
                    longlong2 vq = vr[i * 4 + e];   // one LDS.128, 4 ffma2
                    a0 = ffma2(qpa[2*i],   (u64)vq.x, a0);
                    a1 = ffma2(qpa[2*i+1], (u64)vq.y, a1);
                    b0 = ffma2(qpb[2*i],   (u64)vq.x, b0);
                    b1 = ffma2(qpb[2*i+1], (u64)vq.y, b1);
                }
                float2 x0 = unpk(a0), x1 = unpk(a1);
                float2 y0 = unpk(b0), y1 = unpk(b1);
                pa[j] = (x0.x + x0.y) + (x1.x + x1.y);
                pb[j] = (y0.x + y0.y) + (y1.x + y1.y);
            }

            // ---- 4x4 e<->key transpose (both rows) ----
            {
                float a1v = elo1 ? pa[1] : pa[0];
                float a3v = elo1 ? pa[3] : pa[2];
                float b1v = elo1 ? pb[1] : pb[0];
                float b3v = elo1 ? pb[3] : pb[2];
                a1v = __shfl_xor_sync(0xffffffffu, a1v, 8);
                a3v = __shfl_xor_sync(0xffffffffu, a3v, 8);
                b1v = __shfl_xor_sync(0xffffffffu, b1v, 8);
                b3v = __shfl_xor_sync(0xffffffffu, b3v, 8);
                if (elo1) { pa[1] = a1v; pa[3] = a3v; pb[1] = b1v; pb[3] = b3v; }
                else      { pa[0] = a1v; pa[2] = a3v; pb[0] = b1v; pb[2] = b3v; }
            }
            {
                float a2v = elo2 ? pa[2] : pa[0];
                float a3v = elo2 ? pa[3] : pa[1];
                float b2v = elo2 ? pb[2] : pb[0];
                float b3v = elo2 ? pb[3] : pb[1];
                a2v = __shfl_xor_sync(0xffffffffu, a2v, 16);
                a3v = __shfl_xor_sync(0xffffffffu, a3v, 16);
                b2v = __shfl_xor_sync(0xffffffffu, b2v, 16);
                b3v = __shfl_xor_sync(0xffffffffu, b3v, 16);
                if (elo2) { pa[2] = a2v; pa[3] = a3v; pb[2] = b2v; pb[3] = b3v; }
                else      { pa[0] = a2v; pa[1] = a3v; pb[0] = b2v; pb[1] = b3v; }
            }
            float sA = (pa[0] + pa[1]) + (pa[2] + pa[3]);  // full dot, key tt0+e
            float sB = (pb[0] + pb[1]) + (pb[2] + pb[3]);

            // ---- Softmax over 8 heads (both rows; |s| small: no max-sub) ----
            float exA = __expf(sA) * ebqA;
            float exB = __expf(sB) * ebqB;
            float smA = exA, smB = exB;
            smA += __shfl_xor_sync(0xffffffffu, smA, 1);
            smB += __shfl_xor_sync(0xffffffffu, smB, 1);
            smA += __shfl_xor_sync(0xffffffffu, smA, 2);
            smB += __shfl_xor_sync(0xffffffffu, smB, 2);
            smA += __shfl_xor_sync(0xffffffffu, smA, 4);
            smB += __shfl_xor_sync(0xffffffffu, smB, 4);
            float wA[4], wB[4];
            wA[0] = __fdividef(exA, smA);   // weight of key tt0+e
            wB[0] = __fdividef(exB, smB);

            // ---- Allgather weights across e: w[k] = weight of key tt0+(e^k)
            wA[1] = __shfl_xor_sync(0xffffffffu, wA[0], 8);
            wB[1] = __shfl_xor_sync(0xffffffffu, wB[0], 8);
            wA[2] = __shfl_xor_sync(0xffffffffu, wA[0], 16);
            wB[2] = __shfl_xor_sync(0xffffffffu, wB[0], 16);
            wA[3] = __shfl_xor_sync(0xffffffffu, wA[1], 16);
            wB[3] = __shfl_xor_sync(0xffffffffu, wB[1], 16);

            // ---- Phase B: rank-4 context update, both rows per V load ----
            #pragma unroll
            for (int k = 0; k < 4; ++k) {
                u64 wpa = pk2(wA[k]);
                u64 wpb = pk2(wB[k]);
                const longlong2* vr = Vs + (tt0 + (e ^ k)) * 16;
                #pragma unroll
                for (int i = 0; i < 4; ++i) {
                    longlong2 vq = vr[i * 4 + e];   // one LDS.128, 4 ffma2
                    cta[2*i]   = ffma2(wpa, (u64)vq.x, cta[2*i]);
                    cta[2*i+1] = ffma2(wpa, (u64)vq.y, cta[2*i+1]);
                    ctb[2*i]   = ffma2(wpb, (u64)vq.x, ctb[2*i]);
                    ctb[2*i+1] = ffma2(wpb, (u64)vq.y, ctb[2*i+1]);
                }
            }
        }
        __syncthreads();   // protect buffer before next prefetch overwrites it
    }

    // out[b, q, h*64 + chunk(4i+e)] for both rows
    longlong2* opA = (longlong2*)(out + (size_t)rowA * DD + h * DH);
    longlong2* opB = (longlong2*)(out + (size_t)rowB * DD + h * DH);
    #pragma unroll
    for (int i = 0; i < 4; ++i) {
        longlong2 va, vb;
        va.x = (long long)cta[2*i];  va.y = (long long)cta[2*i+1];
        vb.x = (long long)ctb[2*i];  vb.y = (long long)ctb[2*i+1];
        opA[i * 4 + e] = va;
        opB[i * 4 + e] = vb;
    }
}

extern "C" void kernel_launch(void* const* d_in, const int* in_sizes, int n_in,
                              void* d_out, int out_size) {
    const float* query  = (const float*)d_in[0];   // [2,2048,512]
    const float* value  = (const float*)d_in[1];   // [2,2048,64]
    const float* conv_w = (const float*)d_in[2];   // [512,64,1]
    const float* conv_b = (const float*)d_in[3];   // [512]
    float* out = (float*)d_out;                    // [2,2048,512]

    prep_kernel<<<BB * TT / TQ1, 256>>>(query, conv_w, conv_b);
    dim3 grid(TT / TQ, BB);
    attn_kernel<<<grid, 256>>>(value, out);
}